// round 9
// baseline (speedup 1.0000x reference)
#include <cuda_runtime.h>
#include <cuda_bf16.h>
#include <cstdint>

// ============================================================================
// PatchMerged: Haar-DWT2 + LayerNorm + Linear, fused into one tf32 GEMM over
// RAW x data using classic mma.sync (sm_80 path — the harness targets base
// sm_103, so tcgen05/TMEM are unavailable).
//
//   out[row, d] = rstd * (X @ Wf)[row, d] + (-rstd*mu) * S1[d] + S0[d]
//   mu  = 2 * (sum of 'a' samples) / 384
//   var = (sum of squares of all 384 raw samples)/384 - mu^2  (Haar orthonormal)
// ============================================================================

#define NOUT 192
#define KTOT 384
#define NCHUNK 12     // K chunks of 32 floats (8 channels x 4 positions)

// ---- dynamic SMEM layout (bytes) ----
#define SM_A0    0        // A buf: 128 rows x 128B (16B-granule XOR swizzle)
#define SM_A1    16384
#define SM_B0    32768    // B buf: 192 rows x 128B
#define SM_B1    57344
#define SM_RED   81920    // float2 red[128][2]
#define SM_S1    83968    // float S1[192]
#define SM_S0    84736    // float S0[192]
#define SM_RSTD  85504    // float rstd[128]
#define SM_ALPHA 86016    // float alpha[128]
#define SM_TOTAL 86528

// ---- precomputed weights (recomputed every launch; deterministic) ----
__device__ __align__(16) float g_WfT[NOUT * KTOT];   // [d][k], k = c*4 + p, tf32-rounded
__device__ float g_S1[NOUT];
__device__ float g_S0[NOUT];

// ============================================================================
// helpers
// ============================================================================
__device__ __forceinline__ uint32_t s2u(const void* p) {
    uint32_t a;
    asm("{ .reg .u64 t; cvta.to.shared.u64 t, %1; cvt.u32.u64 %0, t; }"
        : "=r"(a) : "l"(p));
    return a;
}
__device__ __forceinline__ void cp_async8(uint32_t s, const void* g) {
    asm volatile("cp.async.ca.shared.global [%0], [%1], 8;" :: "r"(s), "l"(g));
}
__device__ __forceinline__ void cp_async16(uint32_t s, const void* g) {
    asm volatile("cp.async.ca.shared.global [%0], [%1], 16;" :: "r"(s), "l"(g));
}
__device__ __forceinline__ float tf32_rna(float x) {
    float y;
    asm("cvt.rna.tf32.f32 %0, %1;" : "=f"(y) : "f"(x));
    return y;
}
__device__ __forceinline__ uint32_t lds_u32(uint32_t a) {
    uint32_t v;
    asm volatile("ld.shared.b32 %0, [%1];" : "=r"(v) : "r"(a));
    return v;
}
__device__ __forceinline__ float lds_f32(uint32_t a) {
    float v;
    asm volatile("ld.shared.f32 %0, [%1];" : "=f"(v) : "r"(a));
    return v;
}

#define MMA_TF32(d, a, b0r, b1r)                                            \
    asm volatile(                                                           \
        "mma.sync.aligned.m16n8k8.row.col.f32.tf32.tf32.f32 "               \
        "{%0,%1,%2,%3}, {%4,%5,%6,%7}, {%8,%9}, {%0,%1,%2,%3};"             \
        : "+f"((d)[0]), "+f"((d)[1]), "+f"((d)[2]), "+f"((d)[3])            \
        : "r"((a)[0]), "r"((a)[1]), "r"((a)[2]), "r"((a)[3]),               \
          "r"(b0r), "r"(b1r))

// ============================================================================
// Prep kernels: fold Haar signs + norm_w into WfT (tf32-rounded); S1, S0.
//   Wf[(c,p), d] = 0.5 * sum_q sign[q][p] * norm_w[q*96+c] * w_red[q*96+c, d]
//   S1[d] = sum_j norm_w[j]*w_red[j,d];  S0[d] = sum_j norm_b[j]*w_red[j,d]
// ============================================================================
__global__ void prep_wfold(const float* __restrict__ nw, const float* __restrict__ w) {
    int c = blockIdx.x;    // 0..95
    int d = threadIdx.x;   // 0..191
    float w0 = nw[0 * 96 + c] * w[(0 * 96 + c) * NOUT + d];
    float w1 = nw[1 * 96 + c] * w[(1 * 96 + c) * NOUT + d];
    float w2 = nw[2 * 96 + c] * w[(2 * 96 + c) * NOUT + d];
    float w3 = nw[3 * 96 + c] * w[(3 * 96 + c) * NOUT + d];
    float* dst = &g_WfT[d * KTOT + c * 4];
    dst[0] = tf32_rna(0.5f * (w0 + w1 + w2 + w3));   // p = a
    dst[1] = tf32_rna(0.5f * (w0 + w1 - w2 - w3));   // p = b
    dst[2] = tf32_rna(0.5f * (w0 - w1 + w2 - w3));   // p = c
    dst[3] = tf32_rna(0.5f * (w0 - w1 - w2 + w3));   // p = d
}

__global__ void prep_s(const float* __restrict__ nw, const float* __restrict__ nb,
                       const float* __restrict__ w) {
    int d = threadIdx.x;
    float s1 = 0.f, s0 = 0.f;
    for (int j = 0; j < KTOT; j++) {
        float wv = w[j * NOUT + d];
        s1 += nw[j] * wv;
        s0 += nb[j] * wv;
    }
    g_S1[d] = s1;
    g_S0[d] = s0;
}

// ============================================================================
// Main kernel. CTA = one (b, i): 128 rows x 192 cols. 8 warps: 2(M) x 4(N),
// warp tile 64x48 = 4x6 m16n8k8 tiles, 96 fp32 accums/thread.
// ============================================================================
__global__ void __launch_bounds__(256)
pm_main(const float* __restrict__ x, float* __restrict__ out) {
    extern __shared__ char smem[];
    uint32_t sb = s2u(smem);
    int tid = threadIdx.x, lane = tid & 31, wid = tid >> 5;
    int wm = wid & 1, wn = wid >> 1;       // warp grid 2 x 4
    int q = lane >> 2, p = lane & 3;       // quad row / thread-in-quad
    int bx = blockIdx.x;
    int b = bx >> 7, i = bx & 127;
    const float* xb = x + (size_t)b * 96 * 65536 + (size_t)(2 * i) * 256;

    float* S1s = (float*)(smem + SM_S1);
    float* S0s = (float*)(smem + SM_S0);
    if (tid < NOUT) { S1s[tid] = g_S1[tid]; S0s[tid] = g_S0[tid]; }

    // A loader: chunk kc covers channels 8kc..8kc+7. k-in-chunk = cc*4 + pos,
    // pos = {a,b,c,d}. (a,b) is one 8B word at x[c,2i,2j]; (c,d) at x[c,2i+1,2j].
    // SMEM row j = 128B; 16B-granule XOR swizzle: granule g -> g ^ (j&7).
    auto loadA = [&](int kc, uint32_t base) {
#pragma unroll
        for (int it = 0; it < 8; ++it) {
            int idx = it * 256 + tid;          // 0..2047
            int j = idx & 127;
            int qq = idx >> 7;                 // 0..15
            int cc = qq >> 1, h = qq & 1;
            const float* g = xb + (size_t)(kc * 8 + cc) * 65536 + h * 256 + 2 * j;
            uint32_t off = (uint32_t)(j * 128 + (((cc ^ (j & 7))) << 4) + h * 8);
            cp_async8(base + off, g);
        }
    };
    // B loader: WfT rows d (192 x 32 floats), 16B units u, same swizzle by d.
    auto loadB = [&](int kc, uint32_t base) {
        const float* g0 = g_WfT + kc * 32;
#pragma unroll
        for (int it = 0; it < 6; ++it) {
            int idx = it * 256 + tid;          // 0..1535
            int d = idx >> 3, u = idx & 7;
            uint32_t off = (uint32_t)(d * 128 + ((u ^ (d & 7)) << 4));
            cp_async16(base + off, g0 + (size_t)d * KTOT + u * 4);
        }
    };

    loadA(0, sb + SM_A0);
    loadB(0, sb + SM_B0);
    asm volatile("cp.async.commit_group;" ::: "memory");

    float acc[4][6][4];
#pragma unroll
    for (int mt = 0; mt < 4; ++mt)
#pragma unroll
        for (int nt = 0; nt < 6; ++nt)
#pragma unroll
            for (int e = 0; e < 4; ++e) acc[mt][nt][e] = 0.f;

    // per-thread fragment base offsets (swizzle term added per k-step)
    uint32_t offA[4], offB[6];
#pragma unroll
    for (int mt = 0; mt < 4; ++mt)
        offA[mt] = (uint32_t)((wm * 64 + mt * 16 + q) * 128 + p * 4);
#pragma unroll
    for (int nt = 0; nt < 6; ++nt)
        offB[nt] = (uint32_t)((wn * 48 + nt * 8 + q) * 128 + p * 4);

    // stats: thread t handles row sr = t>>1, channel-granules sh*4+u
    float suma = 0.f, ssq = 0.f;
    int sr = tid >> 1, sh = tid & 1;
    uint32_t statbase = (uint32_t)(sr * 128);

    for (int n = 0; n < NCHUNK; ++n) {
        __syncthreads();   // all reads of chunk n-1 done before overwriting its buffer
        if (n + 1 < NCHUNK) {
            uint32_t ab = sb + (((n + 1) & 1) ? SM_A1 : SM_A0);
            uint32_t bb = sb + (((n + 1) & 1) ? SM_B1 : SM_B0);
            loadA(n + 1, ab);
            loadB(n + 1, bb);
            asm volatile("cp.async.commit_group;" ::: "memory");
            asm volatile("cp.async.wait_group 1;" ::: "memory");
        } else {
            asm volatile("cp.async.wait_group 0;" ::: "memory");
        }
        __syncthreads();   // chunk n visible to all threads

        uint32_t abase = sb + ((n & 1) ? SM_A1 : SM_A0);
        uint32_t bbase = sb + ((n & 1) ? SM_B1 : SM_B0);

        // ---- stats from landed A chunk (each 16B granule = one channel's abcd)
#pragma unroll
        for (int u = 0; u < 4; ++u) {
            int cc = sh * 4 + u;
            uint32_t a = abase + statbase + (uint32_t)(((cc ^ (sr & 7)) << 4));
            float vx, vy, vz, vw;
            asm volatile("ld.shared.v4.f32 {%0,%1,%2,%3}, [%4];"
                         : "=f"(vx), "=f"(vy), "=f"(vz), "=f"(vw) : "r"(a));
            suma += vx;                                  // 'a' sample
            ssq += vx * vx + vy * vy + vz * vz + vw * vw;
        }

        // ---- 4 k-steps of m16n8k8 tf32 mma
#pragma unroll
        for (int ks = 0; ks < 4; ++ks) {
            uint32_t sw0 = (uint32_t)(((2 * ks) ^ q) << 4);      // k = 8ks + p
            uint32_t sw1 = (uint32_t)(((2 * ks + 1) ^ q) << 4);  // k = 8ks + 4 + p
            uint32_t bf[6][2];
#pragma unroll
            for (int nt = 0; nt < 6; ++nt) {
                bf[nt][0] = lds_u32(bbase + offB[nt] + sw0);
                bf[nt][1] = lds_u32(bbase + offB[nt] + sw1);
            }
            uint32_t af[4][4];
#pragma unroll
            for (int mt = 0; mt < 4; ++mt) {
                float a0 = lds_f32(abase + offA[mt] + sw0);
                float a1 = lds_f32(abase + offA[mt] + 1024 + sw0);   // row + 8
                float a2 = lds_f32(abase + offA[mt] + sw1);
                float a3 = lds_f32(abase + offA[mt] + 1024 + sw1);
                af[mt][0] = __float_as_uint(tf32_rna(a0));
                af[mt][1] = __float_as_uint(tf32_rna(a1));
                af[mt][2] = __float_as_uint(tf32_rna(a2));
                af[mt][3] = __float_as_uint(tf32_rna(a3));
            }
#pragma unroll
            for (int mt = 0; mt < 4; ++mt)
#pragma unroll
                for (int nt = 0; nt < 6; ++nt)
                    MMA_TF32(acc[mt][nt], af[mt], bf[nt][0], bf[nt][1]);
        }
    }

    // ---- LayerNorm stats reduction -> per-row rstd / alpha
    ((float2*)(smem + SM_RED))[sr * 2 + sh] = make_float2(suma, ssq);
    __syncthreads();
    if (tid < 128) {
        float2 p0 = ((float2*)(smem + SM_RED))[tid * 2 + 0];
        float2 p1 = ((float2*)(smem + SM_RED))[tid * 2 + 1];
        float sa = p0.x + p1.x;
        float sq = p0.y + p1.y;
        float mu = sa * (2.0f / 384.0f);
        float var = sq * (1.0f / 384.0f) - mu * mu;
        float rstd = rsqrtf(var + 1e-5f);
        ((float*)(smem + SM_RSTD))[tid] = rstd;
        ((float*)(smem + SM_ALPHA))[tid] = -rstd * mu;
    }
    __syncthreads();

    // ---- epilogue: affine + store (8B stores, 32B-sector aligned per quad)
    const float* rstd_s = (const float*)(smem + SM_RSTD);
    const float* alpha_s = (const float*)(smem + SM_ALPHA);
    float* outb = out + (size_t)bx * 128 * NOUT;   // global row = bx*128 + jrow
#pragma unroll
    for (int mt = 0; mt < 4; ++mt) {
        int r0 = wm * 64 + mt * 16 + q;
        int r1 = r0 + 8;
        float rs0 = rstd_s[r0], al0 = alpha_s[r0];
        float rs1 = rstd_s[r1], al1 = alpha_s[r1];
#pragma unroll
        for (int nt = 0; nt < 6; ++nt) {
            int c0 = wn * 48 + nt * 8 + 2 * p;
            float s1a = S1s[c0], s1b = S1s[c0 + 1];
            float s0a = S0s[c0], s0b = S0s[c0 + 1];
            float2 v0, v1;
            v0.x = fmaf(rs0, acc[mt][nt][0], fmaf(al0, s1a, s0a));
            v0.y = fmaf(rs0, acc[mt][nt][1], fmaf(al0, s1b, s0b));
            v1.x = fmaf(rs1, acc[mt][nt][2], fmaf(al1, s1a, s0a));
            v1.y = fmaf(rs1, acc[mt][nt][3], fmaf(al1, s1b, s0b));
            *(float2*)(outb + (size_t)r0 * NOUT + c0) = v0;
            *(float2*)(outb + (size_t)r1 * NOUT + c0) = v1;
        }
    }
}

// ============================================================================
// Launch
// ============================================================================
extern "C" void kernel_launch(void* const* d_in, const int* in_sizes, int n_in,
                              void* d_out, int out_size) {
    const float* x  = (const float*)d_in[0];   // [16, 96, 256, 256]
    const float* nw = (const float*)d_in[1];   // [384]
    const float* nb = (const float*)d_in[2];   // [384]
    const float* w  = (const float*)d_in[3];   // [384, 192]
    float* out = (float*)d_out;                // [16, 16384, 192]
    (void)in_sizes; (void)n_in; (void)out_size;

    prep_wfold<<<96, 192>>>(nw, w);
    prep_s<<<1, 192>>>(nw, nb, w);

    cudaFuncSetAttribute(pm_main, cudaFuncAttributeMaxDynamicSharedMemorySize,
                         SM_TOTAL);
    pm_main<<<2048, 256, SM_TOTAL>>>(x, out);
}